// round 12
// baseline (speedup 1.0000x reference)
#include <cuda_runtime.h>

// GumbelVQ forward on GB300 (sm_103a).  Best passing: R6 @ 258.6us.
//
//  - st = y_hard numerically  =>  z_q = embedding[argmax_k(logits + gumbel)]
//  - JAX (threefry_partitionable=True) counter-mode noise: for linear element
//    index i over (N,K):  (o0,o1) = threefry2x32(key=(0,42), (0,i)),
//    bits = o0 ^ o1.  u = bitcast((bits>>9)|0x3f800000)-1 clamped to 1e-20.
//    gumbel = -log(-log u).  argmax first-occurrence.
//  - Filter: g <= -ilogb(1-u)*ln2; only candidates that can beat the warp's
//    running max pay exact logs.
//  - R9/R11: kernel is ALU-PIPE bound (SHF/LOP3/IADD3 all on alu, rt=2).
//    Move rotations to the fma pipe: rotl(x,r) = {hi,lo} of x * 2^r via
//    mul.wide.u32 (IMAD.WIDE, fma pipe); (lo|hi)^x0 is ONE LOP3.  The eight
//    multipliers arrive packed in two uint4 kernel args so ptxas cannot
//    strength-reduce the multiply back into SHF.  2-stage final reduction
//    (32 blocks + 1-warp combine) replaces the 16us single-block reduction.

#define NUM_CODES 8192
#define NROWS     8192

__device__ float g_row_commit[NROWS];
__device__ int   g_counts[NUM_CODES];     // zero at start; re-zeroed each run
__device__ float g_part_plog[32];
__device__ float g_part_csum[32];
__device__ int   g_part_used[32];

// rotate-left via widening multiply (IMAD.WIDE, fma pipe) + fused (lo|hi)^c
// in a single LOP3 (alu pipe).  mul must be a runtime value = 1u<<r.
__device__ __forceinline__ unsigned rotx(unsigned x, unsigned mul, unsigned c) {
    unsigned long long w;
    asm("mul.wide.u32 %0, %1, %2;" : "=l"(w) : "r"(x), "r"(mul));
    return ((unsigned)w | (unsigned)(w >> 32)) ^ c;
}

// threefry2x32, key (0,42), input (0, i), 20 rounds, output o0^o1.
// Key injections folded into the adjacent adds.
__device__ __forceinline__ unsigned tf_bits(unsigned i, uint4 ma, uint4 mb) {
    const unsigned C = 0x1BD11BF0u;          // 0 ^ 42 ^ 0x1BD11BDA
    unsigned x0, x1;
    x1 = i + 42u;
    x0 = x1;                                 // round-1 add with x0 = 0
    x1 = rotx(x1, ma.x, x0);
    x0 += x1; x1 = rotx(x1, ma.y, x0);
    x0 += x1; x1 = rotx(x1, ma.z, x0);
    x0 += x1; x1 = rotx(x1, ma.w, x0);
    x1 += C + 1u;                            // inj1: x1 += ks[2]+1
    x0 += 42u + x1;                          // inj1: x0 += ks[1], folded
    x1 = rotx(x1, mb.x, x0);
    x0 += x1; x1 = rotx(x1, mb.y, x0);
    x0 += x1; x1 = rotx(x1, mb.z, x0);
    x0 += x1; x1 = rotx(x1, mb.w, x0);
    x1 += 2u;                                // inj2: x1 += ks[0]+2
    x0 += C + x1;                            // inj2: x0 += ks[2], folded
    x1 = rotx(x1, ma.x, x0);
    x0 += x1; x1 = rotx(x1, ma.y, x0);
    x0 += x1; x1 = rotx(x1, ma.z, x0);
    x0 += x1; x1 = rotx(x1, ma.w, x0);
    x1 += 45u;                               // inj3: x1 += ks[1]+3
    x0 += x1;                                // inj3: x0 += ks[0] = 0
    x1 = rotx(x1, mb.x, x0);
    x0 += x1; x1 = rotx(x1, mb.y, x0);
    x0 += x1; x1 = rotx(x1, mb.z, x0);
    x0 += x1; x1 = rotx(x1, mb.w, x0);
    x1 += C + 4u;                            // inj4: x1 += ks[2]+4
    x0 += 42u + x1;                          // inj4: x0 += ks[1], folded
    x1 = rotx(x1, ma.x, x0);
    x0 += x1; x1 = rotx(x1, ma.y, x0);
    x0 += x1; x1 = rotx(x1, ma.z, x0);
    x0 += x1; x1 = rotx(x1, ma.w, x0);
    return (x0 + C) ^ (x1 + 5u);             // inj5 (+C, +5) and xor-fold
}

// exact gumbel from f = 1+u in [1,2): winners have u~1, use log1p there so the
// inner log keeps full relative accuracy even under fast-math.
__device__ __forceinline__ float gumbel_exact(float f) {
    float u = fmaxf(f - 1.0f, 1e-20f);
    float e = (f > 1.5f) ? (-log1pf(f - 2.0f)) : (-logf(u));
    return -logf(e);
}

// ub(gumbel) precursor: fe = -ilogb(1-u) as float, via exponent-bias trick.
__device__ __forceinline__ float ub_fe(float f) {
    const float v = 2.0f - f;                               // = 1-u (Sterbenz)
    const int   e = 127 - (int)(__float_as_uint(v) >> 23);  // 0..23
    return __uint_as_float((unsigned)e | 0x4B000000u) - 8388608.0f;
}

__global__ void __launch_bounds__(256, 2) vq_argmax_kernel(
    const float* __restrict__ z_e,
    const float* __restrict__ emb,
    const float* __restrict__ proj,
    float* __restrict__ out,
    int has_idx, uint4 ma, uint4 mb)
{
    const int lane = threadIdx.x & 31;
    const int warp = threadIdx.x >> 5;
    const int n    = blockIdx.x * 8 + warp;       // one row per warp
    const int b    = n >> 10, hw = n & 1023;      // z_e is (8, 8, 32, 32)

    float z[8];
#pragma unroll
    for (int d = 0; d < 8; d++)
        z[d] = z_e[b * 8192 + d * 1024 + hw];

    const float NEG = -3.0e38f;
    float madj = NEG;                 // (warp running max) - 4e-6 slack
    float best = NEG;
    int   bi   = 0;
    unsigned cnt = (unsigned)n * (unsigned)NUM_CODES + (unsigned)lane;
    const float4* __restrict__ proj4 = (const float4*)proj;

    for (int j = 0; j < NUM_CODES / 32; j += 4) {
        const int kb = j * 32 + lane;

        unsigned bits[4];
#pragma unroll
        for (int c = 0; c < 4; c++)           // 4 independent chains (ILP)
            bits[c] = tf_bits(cnt + 32u * c, ma, mb);
        cnt += 128u;

        float f[4], fe[4], l[4];
#pragma unroll
        for (int c = 0; c < 4; c++) {
            f[c]  = __uint_as_float((bits[c] >> 9) | 0x3f800000u);
            fe[c] = ub_fe(f[c]);
        }
#pragma unroll
        for (int c = 0; c < 4; c++) {
            const int k = kb + 32 * c;
            const float4 wa = __ldg(proj4 + k * 2);
            const float4 wb = __ldg(proj4 + k * 2 + 1);
            float s = z[0] * wa.x;
            s = fmaf(z[1], wa.y, s); s = fmaf(z[2], wa.z, s);
            s = fmaf(z[3], wa.w, s); s = fmaf(z[4], wb.x, s);
            s = fmaf(z[5], wb.y, s); s = fmaf(z[6], wb.z, s);
            s = fmaf(z[7], wb.w, s);
            l[c] = s;
        }

        // 0.69314724 > ln2 rounds the bound up; madj carries -4e-6 slack so
        // FFMA rounding can never drop a true winner.
        bool p[4]; bool any = false;
#pragma unroll
        for (int c = 0; c < 4; c++) {
            p[c] = fmaf(fe[c], 0.69314724f, l[c]) > madj;
            any |= p[c];
        }
        if (__ballot_sync(0xffffffffu, any)) {
            float sm = NEG;
#pragma unroll
            for (int c = 0; c < 4; c++) {        // ascending k: first-occ kept
                if (p[c]) {
                    float s = l[c] + gumbel_exact(f[c]);
                    if (s > best) { best = s; bi = kb + 32 * c; }
                    sm = fmaxf(sm, s);
                }
            }
#pragma unroll
            for (int o = 16; o > 0; o >>= 1)
                sm = fmaxf(sm, __shfl_xor_sync(0xffffffffu, sm, o));
            sm -= 4e-6f;
            if (sm > madj) madj = sm;
        }
    }

    // cross-lane argmax; ties -> smaller k (first occurrence, jnp.argmax)
#pragma unroll
    for (int o = 16; o > 0; o >>= 1) {
        float ob = __shfl_xor_sync(0xffffffffu, best, o);
        int   oi = __shfl_xor_sync(0xffffffffu, bi,   o);
        if (ob > best || (ob == best && oi < bi)) { best = ob; bi = oi; }
    }

    // outputs: z_q gather, per-row commit sum, counts, idx
    float sq = 0.0f;
    if (lane < 8) {
        float ev = emb[bi * 8 + lane];
        out[b * 8192 + lane * 1024 + hw] = ev;
        float dd = z[lane] - ev;
        sq = dd * dd;
    }
#pragma unroll
    for (int o = 16; o > 0; o >>= 1)
        sq += __shfl_xor_sync(0xffffffffu, sq, o);
    if (lane == 0) {
        g_row_commit[n] = sq;
        atomicAdd(&g_counts[bi], 1);
        if (has_idx) out[65536 + n] = (float)bi;
    }
}

// stage 1: 32 blocks, each reduces a 256-code slice (and re-zeros g_counts
// so the next graph replay starts clean).
__global__ void __launch_bounds__(256) vq_partial_kernel() {
    __shared__ float sp[256];
    __shared__ float sc[256];
    __shared__ int   su[256];
    const int t = threadIdx.x;
    const int k = blockIdx.x * 256 + t;

    int c = g_counts[k];
    g_counts[k] = 0;
    float plog = 0.0f;
    int used = 0;
    if (c > 0) {
        float avg = (float)c * (1.0f / 8192.0f);
        plog = avg * logf(avg + 1e-10f);
        used = 1;
    }
    float csum = g_row_commit[k];            // NROWS == NUM_CODES

    sp[t] = plog; sc[t] = csum; su[t] = used;
    __syncthreads();
    for (int s = 128; s > 0; s >>= 1) {
        if (t < s) { sp[t] += sp[t + s]; sc[t] += sc[t + s]; su[t] += su[t + s]; }
        __syncthreads();
    }
    if (t == 0) {
        g_part_plog[blockIdx.x] = sp[0];
        g_part_csum[blockIdx.x] = sc[0];
        g_part_used[blockIdx.x] = su[0];
    }
}

// stage 2: one warp combines the 32 partials.
__global__ void vq_combine_kernel(float* __restrict__ out, int has_scalars) {
    const int t = threadIdx.x;               // 32 threads
    float plog = g_part_plog[t];
    float csum = g_part_csum[t];
    int   used = g_part_used[t];
#pragma unroll
    for (int o = 16; o > 0; o >>= 1) {
        plog += __shfl_xor_sync(0xffffffffu, plog, o);
        csum += __shfl_xor_sync(0xffffffffu, csum, o);
        used += __shfl_xor_sync(0xffffffffu, used, o);
    }
    if (t == 0 && has_scalars) {
        out[73728] = 0.25f * (csum * (1.0f / 65536.0f));   // commit_loss
        out[73729] = expf(-plog);                          // perplexity
        out[73730] = (float)used * (1.0f / 8192.0f);       // usage
    }
}

extern "C" void kernel_launch(void* const* d_in, const int* in_sizes, int n_in,
                              void* d_out, int out_size) {
    const float* z_e  = (const float*)d_in[0];
    const float* emb  = (const float*)d_in[1];
    const float* proj = (const float*)d_in[2];
    float* out = (float*)d_out;
    int has_idx     = (out_size >= 65536 + 8192) ? 1 : 0;
    int has_scalars = (out_size >= 65536 + 8192 + 3) ? 1 : 0;

    uint4 ma = make_uint4(1u << 13, 1u << 15, 1u << 26, 1u << 6);
    uint4 mb = make_uint4(1u << 17, 1u << 29, 1u << 16, 1u << 24);
    vq_argmax_kernel<<<NROWS / 8, 256>>>(z_e, emb, proj, out, has_idx, ma, mb);
    vq_partial_kernel<<<32, 256>>>();
    vq_combine_kernel<<<1, 32>>>(out, has_scalars);
}

// round 17
// speedup vs baseline: 1.2206x; 1.2206x over previous
#include <cuda_runtime.h>

// GumbelVQ forward on GB300 (sm_103a).  Best passing: R6 @ 258.6us.
//
//  - st = y_hard numerically  =>  z_q = embedding[argmax_k(logits + gumbel)]
//  - JAX (threefry_partitionable=True) counter-mode noise: for linear element
//    index i over (N,K):  (o0,o1) = threefry2x32(key=(0,42), (0,i)),
//    bits = o0 ^ o1.  u = bitcast((bits>>9)|0x3f800000)-1 clamped to 1e-20.
//    gumbel = -log(-log u).  argmax first-occurrence.
//  - R12: reverted IMAD.WIDE rotations (R11 regression: 64-bit dest = 2 issue
//    slots + reg pressure).  New: (a) occupancy 2->4 blocks/SM via
//    launch_bounds(256,4); (b) integer filter: L=clz(~bits) gives
//    gumbel <= (L+1)*ln2 in 3 instrs, f reconstructed only for candidates;
//    (c) dot product via packed fma.rn.f32x2 (4 packed FMAs instead of 8).
//    Keep 2-stage reduction (2.7us tail, was 16us).

#define NUM_CODES 8192
#define NROWS     8192
#define LN2UP     0.69314724f

__device__ float g_row_commit[NROWS];
__device__ int   g_counts[NUM_CODES];     // zero at start; re-zeroed each run
__device__ float g_part_plog[32];
__device__ float g_part_csum[32];
__device__ int   g_part_used[32];

__device__ __forceinline__ unsigned rotl(unsigned x, int r) {
    return __funnelshift_l(x, x, r);
}

// threefry2x32, key (0,42), input (0, i), 20 rounds, output o0^o1.
// Key injections folded into the adjacent adds.
__device__ __forceinline__ unsigned tf_bits(unsigned i) {
    const unsigned C = 0x1BD11BF0u;          // 0 ^ 42 ^ 0x1BD11BDA
    unsigned x0, x1;
    x1 = i + 42u;
    x0 = x1;                                 // round-1 add with x0 = 0
    x1 = rotl(x1, 13) ^ x0;
    x0 += x1; x1 = rotl(x1, 15) ^ x0;
    x0 += x1; x1 = rotl(x1, 26) ^ x0;
    x0 += x1; x1 = rotl(x1,  6) ^ x0;
    x1 += C + 1u;                            // inj1: x1 += ks[2]+1
    x0 += 42u + x1;                          // inj1: x0 += ks[1], folded
    x1 = rotl(x1, 17) ^ x0;
    x0 += x1; x1 = rotl(x1, 29) ^ x0;
    x0 += x1; x1 = rotl(x1, 16) ^ x0;
    x0 += x1; x1 = rotl(x1, 24) ^ x0;
    x1 += 2u;                                // inj2: x1 += ks[0]+2
    x0 += C + x1;                            // inj2: x0 += ks[2], folded
    x1 = rotl(x1, 13) ^ x0;
    x0 += x1; x1 = rotl(x1, 15) ^ x0;
    x0 += x1; x1 = rotl(x1, 26) ^ x0;
    x0 += x1; x1 = rotl(x1,  6) ^ x0;
    x1 += 45u;                               // inj3: x1 += ks[1]+3
    x0 += x1;                                // inj3: x0 += ks[0] = 0
    x1 = rotl(x1, 17) ^ x0;
    x0 += x1; x1 = rotl(x1, 29) ^ x0;
    x0 += x1; x1 = rotl(x1, 16) ^ x0;
    x0 += x1; x1 = rotl(x1, 24) ^ x0;
    x1 += C + 4u;                            // inj4: x1 += ks[2]+4
    x0 += 42u + x1;                          // inj4: x0 += ks[1], folded
    x1 = rotl(x1, 13) ^ x0;
    x0 += x1; x1 = rotl(x1, 15) ^ x0;
    x0 += x1; x1 = rotl(x1, 26) ^ x0;
    x0 += x1; x1 = rotl(x1,  6) ^ x0;
    return (x0 + C) ^ (x1 + 5u);             // inj5 (+C, +5) and xor-fold
}

// exact gumbel = -log(-log u), from raw bits (candidates only).
// winners have u~1: log1p there keeps full relative accuracy under fast-math.
__device__ __forceinline__ float gumbel_exact_bits(unsigned bits) {
    const float f = __uint_as_float((bits >> 9) | 0x3f800000u);  // 1+u
    float u = fmaxf(f - 1.0f, 1e-20f);
    float e = (f > 1.5f) ? (-log1pf(f - 2.0f)) : (-logf(u));
    return -logf(e);
}

// packed dual-FMA dot product: 8 floats in 4 f32x2 lanespairs.
__device__ __forceinline__ float dot8(const unsigned long long zp[4],
                                      ulonglong2 wa, ulonglong2 wb) {
    unsigned long long acc;
    asm("mul.rn.f32x2 %0, %1, %2;" : "=l"(acc) : "l"(zp[0]), "l"(wa.x));
    asm("fma.rn.f32x2 %0, %1, %2, %3;" : "=l"(acc) : "l"(zp[1]), "l"(wa.y), "l"(acc));
    asm("fma.rn.f32x2 %0, %1, %2, %3;" : "=l"(acc) : "l"(zp[2]), "l"(wb.x), "l"(acc));
    asm("fma.rn.f32x2 %0, %1, %2, %3;" : "=l"(acc) : "l"(zp[3]), "l"(wb.y), "l"(acc));
    unsigned lo, hi;
    asm("mov.b64 {%0, %1}, %2;" : "=r"(lo), "=r"(hi) : "l"(acc));
    return __uint_as_float(lo) + __uint_as_float(hi);
}

__global__ void __launch_bounds__(256, 4) vq_argmax_kernel(
    const float* __restrict__ z_e,
    const float* __restrict__ emb,
    const float* __restrict__ proj,
    float* __restrict__ out,
    int has_idx)
{
    const int lane = threadIdx.x & 31;
    const int warp = threadIdx.x >> 5;
    const int n    = blockIdx.x * 8 + warp;       // one row per warp
    const int b    = n >> 10, hw = n & 1023;      // z_e is (8, 8, 32, 32)

    float z[8];
    unsigned long long zp[4];
#pragma unroll
    for (int d = 0; d < 8; d++)
        z[d] = z_e[b * 8192 + d * 1024 + hw];
#pragma unroll
    for (int d = 0; d < 4; d++)
        asm("mov.b64 %0, {%1, %2};" : "=l"(zp[d])
            : "r"(__float_as_uint(z[2 * d])), "r"(__float_as_uint(z[2 * d + 1])));

    const float NEG = -3.0e38f;
    // madjc = (running warp max) - LN2UP - slack, so the filter is a single
    // FFMA+compare:  keep iff  L*ln2up + l > madjc
    //   (true score s <= l + (L+1)*ln2 where L = clz(~bits):
    //    1-u in (2^-(L+1), 2^-L]  =>  gumbel <= -log(1-u) < (L+1)*ln2)
    float madjc = NEG;
    float best = NEG;
    int   bi   = 0;
    unsigned cnt = (unsigned)n * (unsigned)NUM_CODES + (unsigned)lane;
    const ulonglong2* __restrict__ proj8 = (const ulonglong2*)proj;

    for (int j = 0; j < NUM_CODES / 32; j += 2) {
        const int k0 = j * 32 + lane;
        const int k1 = k0 + 32;
        const unsigned bits0 = tf_bits(cnt);         // 2 independent chains
        const unsigned bits1 = tf_bits(cnt + 32u);
        cnt += 64u;

        const float fL0 = (float)__clz(~bits0);
        const float fL1 = (float)__clz(~bits1);

        const ulonglong2 wa0 = __ldg(proj8 + k0 * 2);
        const ulonglong2 wb0 = __ldg(proj8 + k0 * 2 + 1);
        const ulonglong2 wa1 = __ldg(proj8 + k1 * 2);
        const ulonglong2 wb1 = __ldg(proj8 + k1 * 2 + 1);
        const float l0 = dot8(zp, wa0, wb0);
        const float l1 = dot8(zp, wa1, wb1);

        const bool p0 = fmaf(fL0, LN2UP, l0) > madjc;
        const bool p1 = fmaf(fL1, LN2UP, l1) > madjc;
        if (__ballot_sync(0xffffffffu, p0 | p1)) {
            float sm = NEG;
            if (p0) {
                float s = l0 + gumbel_exact_bits(bits0);
                if (s > best) { best = s; bi = k0; }
                sm = s;
            }
            if (p1) {                                // after k0: first-occ kept
                float s = l1 + gumbel_exact_bits(bits1);
                if (s > best) { best = s; bi = k1; }
                sm = fmaxf(sm, s);
            }
#pragma unroll
            for (int o = 16; o > 0; o >>= 1)
                sm = fmaxf(sm, __shfl_xor_sync(0xffffffffu, sm, o));
            sm -= (LN2UP + 4e-6f);                   // fold bound offset+slack
            if (sm > madjc) madjc = sm;
        }
    }

    // cross-lane argmax; ties -> smaller k (first occurrence, jnp.argmax)
#pragma unroll
    for (int o = 16; o > 0; o >>= 1) {
        float ob = __shfl_xor_sync(0xffffffffu, best, o);
        int   oi = __shfl_xor_sync(0xffffffffu, bi,   o);
        if (ob > best || (ob == best && oi < bi)) { best = ob; bi = oi; }
    }

    // outputs: z_q gather, per-row commit sum, counts, idx
    float sq = 0.0f;
    if (lane < 8) {
        float ev = emb[bi * 8 + lane];
        out[b * 8192 + lane * 1024 + hw] = ev;
        float dd = z[lane] - ev;
        sq = dd * dd;
    }
#pragma unroll
    for (int o = 16; o > 0; o >>= 1)
        sq += __shfl_xor_sync(0xffffffffu, sq, o);
    if (lane == 0) {
        g_row_commit[n] = sq;
        atomicAdd(&g_counts[bi], 1);
        if (has_idx) out[65536 + n] = (float)bi;
    }
}

// stage 1: 32 blocks, each reduces a 256-code slice (re-zeroing g_counts so
// the next graph replay starts clean).
__global__ void __launch_bounds__(256) vq_partial_kernel() {
    __shared__ float sp[256];
    __shared__ float sc[256];
    __shared__ int   su[256];
    const int t = threadIdx.x;
    const int k = blockIdx.x * 256 + t;

    int c = g_counts[k];
    g_counts[k] = 0;
    float plog = 0.0f;
    int used = 0;
    if (c > 0) {
        float avg = (float)c * (1.0f / 8192.0f);
        plog = avg * logf(avg + 1e-10f);
        used = 1;
    }
    float csum = g_row_commit[k];            // NROWS == NUM_CODES

    sp[t] = plog; sc[t] = csum; su[t] = used;
    __syncthreads();
    for (int s = 128; s > 0; s >>= 1) {
        if (t < s) { sp[t] += sp[t + s]; sc[t] += sc[t + s]; su[t] += su[t + s]; }
        __syncthreads();
    }
    if (t == 0) {
        g_part_plog[blockIdx.x] = sp[0];
        g_part_csum[blockIdx.x] = sc[0];
        g_part_used[blockIdx.x] = su[0];
    }
}

// stage 2: one warp combines the 32 partials.
__global__ void vq_combine_kernel(float* __restrict__ out, int has_scalars) {
    const int t = threadIdx.x;               // 32 threads
    float plog = g_part_plog[t];
    float csum = g_part_csum[t];
    int   used = g_part_used[t];
#pragma unroll
    for (int o = 16; o > 0; o >>= 1) {
        plog += __shfl_xor_sync(0xffffffffu, plog, o);
        csum += __shfl_xor_sync(0xffffffffu, csum, o);
        used += __shfl_xor_sync(0xffffffffu, used, o);
    }
    if (t == 0 && has_scalars) {
        out[73728] = 0.25f * (csum * (1.0f / 65536.0f));   // commit_loss
        out[73729] = expf(-plog);                          // perplexity
        out[73730] = (float)used * (1.0f / 8192.0f);       // usage
    }
}

extern "C" void kernel_launch(void* const* d_in, const int* in_sizes, int n_in,
                              void* d_out, int out_size) {
    const float* z_e  = (const float*)d_in[0];
    const float* emb  = (const float*)d_in[1];
    const float* proj = (const float*)d_in[2];
    float* out = (float*)d_out;
    int has_idx     = (out_size >= 65536 + 8192) ? 1 : 0;
    int has_scalars = (out_size >= 65536 + 8192 + 3) ? 1 : 0;

    vq_argmax_kernel<<<NROWS / 8, 256>>>(z_e, emb, proj, out, has_idx);
    vq_partial_kernel<<<32, 256>>>();
    vq_combine_kernel<<<1, 32>>>(out, has_scalars);
}